// round 7
// baseline (speedup 1.0000x reference)
#include <cuda_runtime.h>
#include <cstdint>

#define NA 896          // anchors
#define NT 896          // threads
#define NSORT 1024      // fallback sort capacity
#define WMAX 14         // ceil(896/64)

// shared memory layout (bytes)
static constexpr int SDET_OFF  = 0;                         // float sdet[NA][17]
static constexpr int KEYS_OFF  = NA * 17 * 4;               // 60928 (8B aligned)
static constexpr int ROWS_OFF  = KEYS_OFF + NSORT * 8;      // 69120 (16B aligned)
static constexpr int SBOX_OFF  = ROWS_OFF + NA * WMAX * 8;  // 169472 (16B aligned)
static constexpr int SAREA_OFF = SBOX_OFF + NA * 16;        // 183808
static constexpr int SV_OFF    = SAREA_OFF + NA * 4;        // 187392  int[0]=V, int[1]=nOut
static constexpr int DESCM_OFF = SV_OFF + 16;               // 187408  u64[128]
static constexpr int DESCC_OFF = DESCM_OFF + 1024;          // 188432  ulonglong2[128]
static constexpr int KEYS2_OFF = DESCC_OFF + 2048;          // 190480  u64[128] sorted keys
static constexpr int SMEM_BYTES = KEYS2_OFF + 1024;         // 191504

// one stage of 32x32 bit transpose (same convention as R6, verified)
__device__ __forceinline__ unsigned bt_stage(unsigned x, int lane, int j, unsigned M) {
    unsigned y = __shfl_xor_sync(0xFFFFFFFFu, x, j);
    if ((lane & j) == 0) x ^= (x ^ (y << j)) & M;
    else                 x ^= (((y ^ (x << j)) & M) >> j);
    return x;
}

__device__ __forceinline__ unsigned bt_full(unsigned x, int lane) {
    x = bt_stage(x, lane, 16, 0xFFFF0000u);
    x = bt_stage(x, lane,  8, 0xFF00FF00u);
    x = bt_stage(x, lane,  4, 0xF0F0F0F0u);
    x = bt_stage(x, lane,  2, 0xCCCCCCCCu);
    x = bt_stage(x, lane,  1, 0xAAAAAAAAu);
    return x;
}

__global__ void __launch_bounds__(NT, 1)
blaze_nms_kernel(const float* __restrict__ raw_boxes,
                 const float* __restrict__ raw_scores,
                 const float* __restrict__ anchors,
                 float* __restrict__ out)
{
    extern __shared__ unsigned char smem[];
    float*              sdet   = (float*)(smem + SDET_OFF);
    unsigned long long* keys   = (unsigned long long*)(smem + KEYS_OFF);
    unsigned long long* rows   = (unsigned long long*)(smem + ROWS_OFF);
    unsigned int*       rows32 = (unsigned int*)(smem + ROWS_OFF);
    float4*             sbox   = (float4*)(smem + SBOX_OFF);
    float*              sarea  = (float*)(smem + SAREA_OFF);
    int*                sV     = (int*)(smem + SV_OFF);
    unsigned long long* descM  = (unsigned long long*)(smem + DESCM_OFF);
    ulonglong2*         descC  = (ulonglong2*)(smem + DESCC_OFF);
    unsigned long long* keys2  = (unsigned long long*)(smem + KEYS2_OFF);

    const int tid  = threadIdx.x;
    const int lane = tid & 31;

    // ---- Issue all global loads FIRST (latency hides init + sync) ----
    const int i = tid;
    const float4* rb = (const float4*)(raw_boxes + (size_t)i * 16);
    float4 r0 = rb[0], r1 = rb[1], r2 = rb[2], r3 = rb[3];
    float4 an = ((const float4*)anchors)[i];
    float sc = raw_scores[i];

    if (tid == 0) { sV[0] = 0; sV[1] = 0; }
    __syncthreads();                                   // sync #1 (under load latency)

    // ---- Decode, sigmoid, threshold, warp-aggregated compaction ----
    {
        const float ax = an.x, ay = an.y, aw = an.z, ah = an.w;
        const float INV = 1.0f / 128.0f;

        float xc = r0.x * INV * aw + ax;
        float yc = r0.y * INV * ah + ay;
        float w  = r0.z * INV * aw;
        float h  = r0.w * INV * ah;
        float d0 = yc - h * 0.5f, d1 = xc - w * 0.5f;
        float d2 = yc + h * 0.5f, d3 = xc + w * 0.5f;

        sc = fminf(fmaxf(sc, -100.0f), 100.0f);
        float s = 1.0f / (1.0f + expf(-sc));           // exact fp32 sigmoid

        bool pass = (s >= 0.75f);
        unsigned m = __ballot_sync(0xFFFFFFFFu, pass);
        if (pass) {
            int leader = __ffs(m) - 1;
            int base;
            if (lane == leader) base = atomicAdd(sV, __popc(m));
            base = __shfl_sync(m, base, leader);
            int slot = base + __popc(m & ((1u << lane) - 1u));

            keys[slot] = ((unsigned long long)__float_as_uint(s) << 32)
                       | ((unsigned long long)(1023 - i) << 10)
                       | (unsigned long long)slot;
            float* d = sdet + slot * 17;               // stride 17: conflict-free
            d[0] = d0; d[1] = d1; d[2] = d2; d[3] = d3;
            d[4]  = r1.x * INV * aw + ax;  d[5]  = r1.y * INV * ah + ay;
            d[6]  = r1.z * INV * aw + ax;  d[7]  = r1.w * INV * ah + ay;
            d[8]  = r2.x * INV * aw + ax;  d[9]  = r2.y * INV * ah + ay;
            d[10] = r2.z * INV * aw + ax;  d[11] = r2.w * INV * ah + ay;
            d[12] = r3.x * INV * aw + ax;  d[13] = r3.y * INV * ah + ay;
            d[14] = r3.z * INV * aw + ax;  d[15] = r3.w * INV * ah + ay;
            d[16] = s;
            sbox[slot]  = make_float4(d0, d1, d2, d3);
            sarea[slot] = (d2 - d0) * (d3 - d1);
        }
    }
    __syncthreads();                                   // sync #2
    const int V = *sV;

    if (V <= 128) {
        // ================= FAST PATH =================
        // Warps 0-3: rank sort (vectorized LDS). Warps 4-19: triangle IOU +
        // minimal transpose (1 barrier, 10 blocks). Warps 20-27: zero output.
        if (tid < 128) {
            if (tid >= V) keys[tid] = (unsigned long long)tid;  // distinct, below real keys
            asm volatile("bar.sync 1, 128;" ::: "memory");
            unsigned long long myKey = keys[tid];
            const ulonglong2* k2 = (const ulonglong2*)keys;
            int rank = 0;
            #pragma unroll 16
            for (int j = 0; j < 64; j++) {
                ulonglong2 kk = k2[j];
                rank += (kk.x > myKey) + (kk.y > myKey);
            }
            keys2[rank] = myKey;                       // descending order
        } else if (tid < 640) {
            int tsk = tid - 128;          // warp covers 32 consecutive s, fixed chunk j
            int s = tsk & 127;
            int j = tsk >> 7;             // q-chunk 0..3
            int a = s >> 5;               // s-block 0..3
            int base = j << 5;
            unsigned int bits = 0u;
            if (j >= a && s < V) {        // strict upper triangle only
                float4 A = sbox[s];
                float areaA = sarea[s];
                int qn = V - base; if (qn > 32) qn = 32;
                if (j > a) {
                    for (int t = 0; t < qn; t++) {
                        float4 B = sbox[base + t];
                        float ih = fmaxf(fminf(A.z, B.z) - fmaxf(A.x, B.x), 0.0f);
                        float iw = fmaxf(fminf(A.w, B.w) - fmaxf(A.y, B.y), 0.0f);
                        float inter = iw * ih;
                        float den = (areaA + sarea[base + t]) - inter;
                        if (inter > 0.3f * den) bits |= (1u << t);
                    }
                } else {                  // diagonal block: fold q > s predicate
                    for (int t = 0; t < qn; t++) {
                        int q = base + t;
                        float4 B = sbox[q];
                        float ih = fmaxf(fminf(A.z, B.z) - fmaxf(A.x, B.x), 0.0f);
                        float iw = fmaxf(fminf(A.w, B.w) - fmaxf(A.y, B.y), 0.0f);
                        float inter = iw * ih;
                        float den = (areaA + sarea[q]) - inter;
                        if ((q > s) && (inter > 0.3f * den)) bits |= (1u << t);
                    }
                }
            }
            rows32[s * 4 + j] = bits;                  // strict-upper U
            asm volatile("bar.sync 2, 512;" ::: "memory");

            // rows = U | U^T, minimal work:
            //   upper blocks (bi<bj): already correct (mirror is zero) — untouched
            //   diag  blocks (w<4):   self |= T(self), in place (own warp only)
            //   lower blocks (6):     = T(upper mirror), plain store (was zero)
            int w = tsk >> 5;             // 0..15
            if (w < 4) {
                unsigned u = rows32[(w * 32 + lane) * 4 + w];
                rows32[(w * 32 + lane) * 4 + w] = u | bt_full(u, lane);
            } else if (w < 10) {
                int idx = w - 4;          // 0..5 -> (bi,bj) in {(1,0),(2,0),(2,1),(3,0),(3,1),(3,2)}
                int bi = (idx >= 3) ? 3 : ((idx >= 1) ? 2 : 1);
                int bj = idx - ((bi * (bi - 1)) >> 1);
                unsigned u = rows32[(bj * 32 + lane) * 4 + bi];   // upper mirror
                rows32[(bi * 32 + lane) * 4 + bj] = bt_full(u, lane);
            }
        } else {
            // zero output: 896*17 = 3808 float4
            float4 z = make_float4(0.f, 0.f, 0.f, 0.f);
            float4* o4 = (float4*)out;
            for (int k = tid - 640; k < 3808; k += 256) o4[k] = z;
        }
        __syncthreads();                               // sync #3

        // ---- Decide loop: warp 0, branchless, ~16cyc carried chain ----
        if (tid < 32 && V > 0) {
            unsigned long long rem0, rem1;
            if (V >= 64) {
                rem0 = ~0ull;
                int r = V - 64;
                rem1 = (r >= 64) ? ~0ull : ((r > 0) ? ((1ull << r) - 1ull) : 0ull);
            } else {
                rem0 = (1ull << V) - 1ull;
                rem1 = 0ull;
            }
            const ulonglong2* rows2 = (const ulonglong2*)rows;
            int count = 0;
            unsigned long long k0 = keys2[0];
            unsigned long long k1 = (V > 1) ? keys2[1] : 0ull;
            int s_cur = (int)(k0 & 0x3FFull);
            int sh_cur = 63 - (s_cur & 63);
            bool lo_cur = (s_cur < 64);
            ulonglong2 rw_cur = rows2[s_cur];
            if (lo_cur) rw_cur.x |= 1ull << s_cur; else rw_cur.y |= 1ull << (s_cur - 64);
            for (int p = 0; p < V; p++) {
                int s = s_cur, sh = sh_cur;
                bool lo = lo_cur;
                ulonglong2 rw = rw_cur;
                // advance pipeline (off the rem-chain)
                k0 = k1;
                if (p + 2 < V) k1 = keys2[p + 2];
                s_cur = (int)(k0 & 0x3FFull);
                sh_cur = 63 - (s_cur & 63);
                lo_cur = (s_cur < 64);
                rw_cur = rows2[s_cur];
                if (lo_cur) rw_cur.x |= 1ull << s_cur; else rw_cur.y |= 1ull << (s_cur - 64);

                // chain: SEL -> SHL -> SAR -> LOP3
                unsigned long long x = (lo ? rem0 : rem1) << sh;
                unsigned long long mask = (unsigned long long)((long long)x >> 63);
                unsigned long long c0 = rw.x & rem0 & mask;    // cluster incl. self
                unsigned long long c1 = rw.y & rem1 & mask;
                rem0 &= ~(rw.x & mask);
                rem1 &= ~(rw.y & mask);
                int n = __popcll(c0) + __popcll(c1);
                descM[count] = ((unsigned long long)(unsigned)n << 32) | (unsigned)s;
                descC[count] = make_ulonglong2(c0, c1);
                count += (int)(x >> 63);
            }
            sV[1] = count;
        }
        __syncthreads();                               // sync #4

        // ---- Parallel emission: one warp per output row ----
        {
            const int nOut = sV[1];
            const int wid = tid >> 5;
            const int li  = (lane < 16) ? lane : 16;
            for (int k = wid; k < nOut; k += 28) {
                unsigned long long m = descM[k];
                int s = (int)(m & 0xFFFFFFFFull);
                int n = (int)(m >> 32);
                float val;
                if (n > 1) {
                    ulonglong2 c = descC[k];
                    float tot = 0.0f, acc = 0.0f;
                    unsigned long long b = c.x;
                    while (b) {
                        int t = __ffsll((long long)b) - 1; b &= b - 1ull;
                        float sw = sdet[t * 17 + 16];
                        tot += sw;
                        acc += sdet[t * 17 + li] * sw;
                    }
                    b = c.y;
                    while (b) {
                        int t = 63 + __ffsll((long long)b); b &= b - 1ull;
                        float sw = sdet[t * 17 + 16];
                        tot += sw;
                        acc += sdet[t * 17 + li] * sw;
                    }
                    val = (lane < 16) ? (acc / tot) : (tot / (float)n);
                } else {
                    val = sdet[s * 17 + li];
                }
                if (lane < 17) out[k * 17 + lane] = val;
            }
        }
    } else {
        // ================= GENERIC FALLBACK (V > 128) =================
        {
            float4 z = make_float4(0.f, 0.f, 0.f, 0.f);
            float4* o4 = (float4*)out;
            for (int k = tid; k < 3808; k += NT) o4[k] = z;
        }
        int Npow = 2;
        while (Npow < V) Npow <<= 1;
        for (int k = V + tid; k < Npow; k += NT) keys[k] = 0ull;
        __syncthreads();
        for (int k = 2; k <= Npow; k <<= 1) {
            for (int j = k >> 1; j > 0; j >>= 1) {
                for (int idx = tid; idx < Npow; idx += NT) {
                    int ixj = idx ^ j;
                    if (ixj > idx) {
                        unsigned long long a = keys[idx], b = keys[ixj];
                        bool asc = ((idx & k) == 0);
                        if (asc ? (a < b) : (a > b)) { keys[idx] = b; keys[ixj] = a; }
                    }
                }
                __syncthreads();
            }
        }
        const int RW = (V + 63) >> 6;
        for (int task = tid; task < V * RW; task += NT) {
            int s = task / RW;
            int w = task - s * RW;
            float4 a = sbox[s];
            float areaA = sarea[s];
            unsigned long long bits = 0ull;
            int base = w << 6;
            int qn = V - base; if (qn > 64) qn = 64;
            for (int t = 0; t < qn; t++) {
                float4 b = sbox[base + t];
                float ih = fmaxf(fminf(a.z, b.z) - fmaxf(a.x, b.x), 0.0f);
                float iw = fmaxf(fminf(a.w, b.w) - fmaxf(a.y, b.y), 0.0f);
                float inter = iw * ih;
                float iou = inter / ((areaA + sarea[base + t]) - inter);
                if (iou > 0.3f) bits |= (1ull << t);
            }
            rows[s * RW + w] = bits;
        }
        __syncthreads();

        if (tid < 32) {
            unsigned long long remw = 0ull;
            if (tid < RW) {
                int left = V - (tid << 6);
                remw = (left >= 64) ? ~0ull : ((left > 0) ? ((1ull << left) - 1ull) : 0ull);
            }
            const int li = (lane < 16) ? lane : 16;
            int count = 0;
            for (int p = 0; p < V; p++) {
                unsigned long long key = keys[p];
                int s = (int)(key & 0x3FFull);
                int ownbit = (int)((remw >> (s & 63)) & 1ull);
                int alive = __shfl_sync(0xFFFFFFFFu, ownbit, s >> 6);
                if (!alive) continue;
                unsigned long long cw = (tid < RW) ? (rows[s * RW + tid] & remw) : 0ull;
                remw &= ~cw;
                if (tid == (s >> 6)) remw &= ~(1ull << (s & 63));
                int nn = __popcll(cw);
                #pragma unroll
                for (int off = 16; off; off >>= 1)
                    nn += __shfl_xor_sync(0xFFFFFFFFu, nn, off);
                float val;
                if (nn > 1) {
                    float tot = 0.0f, acc = 0.0f;
                    for (int w = 0; w < RW; w++) {
                        unsigned long long b = __shfl_sync(0xFFFFFFFFu, cw, w);
                        while (b) {
                            int t = __ffsll((long long)b) - 1; b &= b - 1ull;
                            int slot = (w << 6) + t;
                            float sw = sdet[slot * 17 + 16];
                            tot += sw;
                            acc += sdet[slot * 17 + li] * sw;
                        }
                    }
                    val = (lane < 16) ? (acc / tot) : (tot / (float)nn);
                } else {
                    val = sdet[s * 17 + li];
                }
                if (lane < 17) out[count * 17 + lane] = val;
                count++;
            }
        }
    }
}

extern "C" void kernel_launch(void* const* d_in, const int* in_sizes, int n_in,
                              void* d_out, int out_size) {
    const float* raw_boxes  = (const float*)d_in[0];  // (2048, 896, 16) -- batch 0 only
    const float* raw_scores = (const float*)d_in[1];  // (2048, 896, 1)  -- batch 0 only
    const float* anchors    = (const float*)d_in[2];  // (896, 4)
    float* out = (float*)d_out;                       // (896, 17) float32

    cudaFuncSetAttribute(blaze_nms_kernel,
                         cudaFuncAttributeMaxDynamicSharedMemorySize, SMEM_BYTES);
    blaze_nms_kernel<<<1, NT, SMEM_BYTES>>>(raw_boxes, raw_scores, anchors, out);
}